// round 6
// baseline (speedup 1.0000x reference)
#include <cuda_runtime.h>
#include <cuda_bf16.h>
#include <stdint.h>
#include <math.h>

#define H 256
#define INDIM 128
#define WDIM 512
#define RANKV 10
#define NMAX 50000
#define EMAX 800000
#define SLOPE 0.01f

// ---------------- device scratch ----------------
__device__ float g_styles[3][2 * H * RANKV];
__device__ __nv_bfloat16 g_ah[NMAX * H],  g_al[NMAX * H];
__device__ __nv_bfloat16 g_bh[NMAX * H],  g_bl[NMAX * H];
__device__ __nv_bfloat16 g_xh[NMAX * INDIM], g_xl[NMAX * INDIM];
__device__ __nv_bfloat16 g_Wh[3][H * H],  g_Wl[3][H * H];     // [n][k]
__device__ __nv_bfloat16 g_C1h[H * H],    g_C1l[H * H];       // I + cat1^T [n][k]
__device__ __nv_bfloat16 g_NMh[H * INDIM], g_NMl[H * INDIM];  // fused node-mlp [n][k]
__device__ float g_b2[H];
// CSR scratch
__device__ int g_deg[NMAX];
__device__ int g_off[NMAX + 1];
__device__ int g_cur[NMAX];
__device__ int g_eidx[EMAX];

// ---------------- helpers ----------------
__device__ __forceinline__ void split_bf(float x, __nv_bfloat16& h, __nv_bfloat16& l)
{
    h = __float2bfloat16(x);
    l = __float2bfloat16(x - __bfloat162float(h));
}

__device__ __forceinline__ uint32_t s2u(const void* p)
{
    uint32_t a;
    asm("{ .reg .u64 t; cvta.to.shared.u64 t, %1; cvt.u32.u64 %0, t; }" : "=r"(a) : "l"(p));
    return a;
}

#define LDSM4(r0, r1, r2, r3, addr) \
    asm volatile("ldmatrix.sync.aligned.m8n8.x4.shared.b16 {%0,%1,%2,%3}, [%4];" \
                 : "=r"(r0), "=r"(r1), "=r"(r2), "=r"(r3) : "r"(addr))

#define MMA16816(c, a, b) \
    asm volatile("mma.sync.aligned.m16n8k16.row.col.f32.bf16.bf16.f32 " \
                 "{%0,%1,%2,%3},{%4,%5,%6,%7},{%8,%9},{%0,%1,%2,%3};" \
                 : "+f"((c)[0]), "+f"((c)[1]), "+f"((c)[2]), "+f"((c)[3]) \
                 : "r"((a)[0]), "r"((a)[1]), "r"((a)[2]), "r"((a)[3]), \
                   "r"((b)[0]), "r"((b)[1]))

#define CPA16(dst, src) \
    asm volatile("cp.async.cg.shared.global [%0], [%1], 16;" :: "r"(dst), "l"(src) : "memory")
#define CPA_COMMIT() asm volatile("cp.async.commit_group;" ::: "memory")
#define CPA_WAIT1()  asm volatile("cp.async.wait_group 1;" ::: "memory")
#define CPA_WAIT0()  asm volatile("cp.async.wait_group 0;" ::: "memory")

// ---------------- styles = aw @ w + ab ----------------
__global__ void k_styles(const float* __restrict__ aw0, const float* __restrict__ ab0,
                         const float* __restrict__ aw1, const float* __restrict__ ab1,
                         const float* __restrict__ aw2, const float* __restrict__ ab2,
                         const float* __restrict__ w)
{
    int syn = blockIdx.y;
    const float* aw = (syn == 0) ? aw0 : (syn == 1) ? aw1 : aw2;
    const float* ab = (syn == 0) ? ab0 : (syn == 1) ? ab1 : ab2;
    int row  = blockIdx.x * 8 + (threadIdx.x >> 5);
    int lane = threadIdx.x & 31;
    if (row >= 2 * H * RANKV) return;
    const float* ar = aw + (size_t)row * WDIM;
    float s = 0.f;
    #pragma unroll 4
    for (int t = lane; t < WDIM; t += 32) s += ar[t] * w[t];
    #pragma unroll
    for (int o = 16; o; o >>= 1) s += __shfl_xor_sync(0xffffffffu, s, o);
    if (lane == 0) g_styles[syn][row] = s + ab[row];
}

// ---------------- modulated + row-normalized weight → bf16 split [n][k] ----------------
__global__ void k_modweight(const float* __restrict__ w0,
                            const float* __restrict__ w1,
                            const float* __restrict__ w2)
{
    int syn = blockIdx.y;
    int i   = blockIdx.x;
    int j   = threadIdx.x;
    const float* weight = (syn == 0) ? w0 : (syn == 1) ? w1 : w2;
    const float* st = g_styles[syn];
    __shared__ float L[RANKV];
    __shared__ float red[H];
    if (j < RANKV) L[j] = st[i * RANKV + j];
    __syncthreads();
    const float inv_sqrt_rank = 0.31622776601683794f;
    float mod = 0.f;
    #pragma unroll
    for (int r = 0; r < RANKV; r++) mod += L[r] * st[H * RANKV + r * H + j];
    float wv = weight[i * H + j] * (mod * inv_sqrt_rank + 1.0f);
    red[j] = wv * wv;
    __syncthreads();
    for (int o = 128; o; o >>= 1) { if (j < o) red[j] += red[j + o]; __syncthreads(); }
    float norm = sqrtf(red[0]) + 1e-8f;
    __nv_bfloat16 h, l;
    split_bf(wv / norm, h, l);
    g_Wh[syn][i * H + j] = h;
    g_Wl[syn][i * H + j] = l;
}

// ---------------- C1 = cat1_w + I, split [n][k] ----------------
__global__ void k_prep_c1(const float* __restrict__ cat1_w)
{
    int idx = blockIdx.x * blockDim.x + threadIdx.x;
    int n = idx >> 8, k = idx & 255;
    __nv_bfloat16 h, l;
    split_bf(cat1_w[idx] + ((n == k) ? 1.f : 0.f), h, l);
    g_C1h[idx] = h;
    g_C1l[idx] = l;
}

// ---------------- NM[n][k] = nm_w[n][k] + sum_m cat2_w[n][m]*nm_w[m][k] ----------------
__global__ void k_prep_nm(const float* __restrict__ nm_w,
                          const float* __restrict__ cat2_w)
{
    int n = blockIdx.x;
    int k = threadIdx.x;
    __shared__ float c2[H];
    c2[k] = cat2_w[n * H + k];
    c2[k + 128] = cat2_w[n * H + k + 128];
    __syncthreads();
    float s = nm_w[n * INDIM + k];
    #pragma unroll 8
    for (int m = 0; m < H; m++) s += c2[m] * nm_w[m * INDIM + k];
    __nv_bfloat16 h, l;
    split_bf(s, h, l);
    g_NMh[n * INDIM + k] = h;
    g_NMl[n * INDIM + k] = l;
}

// ---------------- b2[n] ----------------
__global__ void k_prep_b2(const float* __restrict__ cat1_b,
                          const float* __restrict__ cat2_b,
                          const float* __restrict__ nm_b,
                          const float* __restrict__ cat2_w)
{
    int n = threadIdx.x;
    float b = cat1_b[n] + cat2_b[n] + nm_b[n];
    for (int m = 0; m < H; m++) b += cat2_w[n * H + m] * nm_b[m];
    g_b2[n] = b;
}

// ================= CSR build + gather aggregation =================
__global__ void k_zero_deg(int n)
{
    int i = blockIdx.x * blockDim.x + threadIdx.x;
    if (i < n) g_deg[i] = 0;
}

__global__ void k_hist(const int* __restrict__ ei, int E)
{
    int e = blockIdx.x * blockDim.x + threadIdx.x;
    if (e < E) atomicAdd(&g_deg[ei[E + e]], 1);
}

// single-block exclusive scan (warp-shuffle) over g_deg -> g_off, g_cur
__global__ void k_scan(int n)
{
    __shared__ int wsum[32];
    __shared__ int carry;
    int tid = threadIdx.x, lane = tid & 31, wid = tid >> 5;
    if (tid == 0) carry = 0;
    __syncthreads();
    for (int base = 0; base < n; base += 1024) {
        int v = (base + tid < n) ? g_deg[base + tid] : 0;
        int s = v;
        #pragma unroll
        for (int o = 1; o < 32; o <<= 1) {
            int t = __shfl_up_sync(0xffffffffu, s, o);
            if (lane >= o) s += t;
        }
        if (lane == 31) wsum[wid] = s;
        __syncthreads();
        if (wid == 0) {
            int ws = wsum[lane];
            #pragma unroll
            for (int o = 1; o < 32; o <<= 1) {
                int t = __shfl_up_sync(0xffffffffu, ws, o);
                if (lane >= o) ws += t;
            }
            wsum[lane] = ws;
        }
        __syncthreads();
        int woff = (wid > 0) ? wsum[wid - 1] : 0;
        int incl = s + woff + carry;
        int excl = incl - v;
        if (base + tid < n) { g_off[base + tid] = excl; g_cur[base + tid] = excl; }
        __syncthreads();
        if (tid == 1023) carry = incl;
        __syncthreads();
    }
    if (tid == 0) g_off[n] = carry;
}

__global__ void k_fill(const int* __restrict__ ei, int E)
{
    int e = blockIdx.x * blockDim.x + threadIdx.x;
    if (e >= E) return;
    int s = ei[e];
    int d = ei[E + e];
    int p = atomicAdd(&g_cur[d], 1);
    g_eidx[p] = s;
}

// gather: 64 threads per node; fused bias + bf16 split out
__global__ void k_gather(const float* __restrict__ nw,
                         const float* __restrict__ edge_bias,
                         __nv_bfloat16* __restrict__ oh,
                         __nv_bfloat16* __restrict__ ol, int N)
{
    int node = blockIdx.x * 4 + (threadIdx.x >> 6);
    if (node >= N) return;
    int c = (threadIdx.x & 63) * 4;
    int beg = g_off[node], end = g_off[node + 1];
    float4 acc = *(const float4*)(edge_bias + c);
    int i = beg;
    for (; i + 2 <= end; i += 2) {
        int s0 = g_eidx[i], s1 = g_eidx[i + 1];
        float4 v0 = *(const float4*)(nw + (size_t)s0 * H + c);
        float4 v1 = *(const float4*)(nw + (size_t)s1 * H + c);
        acc.x += v0.x; acc.y += v0.y; acc.z += v0.z; acc.w += v0.w;
        acc.x += v1.x; acc.y += v1.y; acc.z += v1.z; acc.w += v1.w;
    }
    if (i < end) {
        int s0 = g_eidx[i];
        float4 v0 = *(const float4*)(nw + (size_t)s0 * H + c);
        acc.x += v0.x; acc.y += v0.y; acc.z += v0.z; acc.w += v0.w;
    }
    __nv_bfloat162 h0 = __floats2bfloat162_rn(acc.x, acc.y);
    __nv_bfloat162 h1 = __floats2bfloat162_rn(acc.z, acc.w);
    __nv_bfloat162 l0 = __floats2bfloat162_rn(acc.x - __low2float(h0), acc.y - __high2float(h0));
    __nv_bfloat162 l1 = __floats2bfloat162_rn(acc.z - __low2float(h1), acc.w - __high2float(h1));
    size_t o = (size_t)node * H + c;
    *(__nv_bfloat162*)(oh + o)     = h0;
    *(__nv_bfloat162*)(oh + o + 2) = h1;
    *(__nv_bfloat162*)(ol + o)     = l0;
    *(__nv_bfloat162*)(ol + o + 2) = l1;
}

// ---------------- fp32 → bf16 hi/lo split (x) ----------------
__global__ void k_split(const float* __restrict__ src,
                        __nv_bfloat16* __restrict__ hi,
                        __nv_bfloat16* __restrict__ lo, int n4)
{
    int idx = blockIdx.x * blockDim.x + threadIdx.x;
    if (idx >= n4) return;
    float4 v = ((const float4*)src)[idx];
    __nv_bfloat162 h0 = __floats2bfloat162_rn(v.x, v.y);
    __nv_bfloat162 h1 = __floats2bfloat162_rn(v.z, v.w);
    __nv_bfloat162 l0 = __floats2bfloat162_rn(v.x - __low2float(h0), v.y - __high2float(h0));
    __nv_bfloat162 l1 = __floats2bfloat162_rn(v.z - __low2float(h1), v.w - __high2float(h1));
    ((__nv_bfloat162*)hi)[idx * 2]     = h0;
    ((__nv_bfloat162*)hi)[idx * 2 + 1] = h1;
    ((__nv_bfloat162*)lo)[idx * 2]     = l0;
    ((__nv_bfloat162*)lo)[idx * 2 + 1] = l1;
}

// ================= bf16 split-3 GEMM, persistent-B in smem =================
// C[M,256] = leaky([A0|A1] @ [B0;B1]^T + bias). B resident for all K; A chunks of 16.
#define A_PITCH 48                 // 32B data + 16B pad: (r*3+c) mod 8 bijective
#define A_TILE (128 * A_PITCH)     // 6144 per (h|l)
#define A_STAGE (2 * A_TILE)       // 12288

__global__ void __launch_bounds__(256)
k_gemm_bf(const __nv_bfloat16* __restrict__ Ah0, const __nv_bfloat16* __restrict__ Al0, int K0,
          const __nv_bfloat16* __restrict__ Ah1, const __nv_bfloat16* __restrict__ Al1, int K1,
          const __nv_bfloat16* __restrict__ Bh0, const __nv_bfloat16* __restrict__ Bl0,
          const __nv_bfloat16* __restrict__ Bh1, const __nv_bfloat16* __restrict__ Bl1,
          float* __restrict__ outF,
          __nv_bfloat16* __restrict__ outH, __nv_bfloat16* __restrict__ outL,
          int M, const float* __restrict__ bias)
{
    extern __shared__ char smem_[];
    const int tid  = threadIdx.x;
    const int lane = tid & 31;
    const int wid  = tid >> 5;
    const int wm   = wid & 1;
    const int wn   = wid >> 1;
    const int gr   = lane >> 2;
    const int tg   = lane & 3;
    const int mBase = blockIdx.x * 128;
    const int nBase = blockIdx.y * 128;

    const int KU  = (K0 + K1) >> 3;          // 16B units per B row
    const int KU0 = K0 >> 3;
    const uint32_t BBYTES = (uint32_t)(128 * KU * 16);
    const uint32_t sBh = s2u(smem_);
    const uint32_t sBl = sBh + BBYTES;
    const uint32_t sA0 = sBh + 2 * BBYTES;

    // ---- B fill: once, XOR-swizzled 16B chunks (group 0) ----
    for (int row = wid; row < 128; row += 8) {
        int n = nBase + row;
        uint32_t rbase = (uint32_t)(row * KU);
        int rx = row & 7;
        for (int c = lane; c < KU; c += 32) {
            const __nv_bfloat16 *sh, *sl;
            if (c < KU0) {
                sh = Bh0 + (size_t)n * K0 + c * 8;
                sl = Bl0 + (size_t)n * K0 + c * 8;
            } else {
                sh = Bh1 + (size_t)n * K1 + (c - KU0) * 8;
                sl = Bl1 + (size_t)n * K1 + (c - KU0) * 8;
            }
            uint32_t off = (rbase + (uint32_t)(c ^ rx)) * 16;
            CPA16(sBh + off, sh);
            CPA16(sBl + off, sl);
        }
    }
    CPA_COMMIT();

    const int T = (K0 + K1) >> 4;            // 16-k chunks
    const int srow = tid >> 1;
    const int sunit = tid & 1;

    auto issue = [&](int t) {
        int kc = t * 16;
        const __nv_bfloat16 *Ah, *Al; int lda;
        if (kc < K0) { Ah = Ah0; Al = Al0; lda = K0; }
        else         { Ah = Ah1; Al = Al1; lda = K1; kc -= K0; }
        int ar = mBase + srow; if (ar >= M) ar = M - 1;
        size_t off = (size_t)ar * lda + kc + sunit * 8;
        uint32_t d = sA0 + (t & 1) * A_STAGE + srow * A_PITCH + sunit * 16;
        CPA16(d,          Ah + off);
        CPA16(d + A_TILE, Al + off);
        CPA_COMMIT();
    };

    float acc[4][4][4];
    #pragma unroll
    for (int i = 0; i < 4; i++)
        #pragma unroll
        for (int j = 0; j < 4; j++)
            #pragma unroll
            for (int q = 0; q < 4; q++) acc[i][j][q] = 0.f;

    // ldmatrix lane components
    const int a_row = (lane & 7) + ((lane >> 3) & 1) * 8;
    const int a_kb  = (lane >> 4) * 16;
    const int b_row = (lane & 7) + ((lane >> 4) & 1) * 8;
    const int b_ku  = (lane >> 3) & 1;

    issue(0);

    for (int t = 0; t < T; t++) {
        if (t + 1 < T) { issue(t + 1); CPA_WAIT1(); }
        else           { CPA_WAIT0(); }
        __syncthreads();

        uint32_t sa = sA0 + (t & 1) * A_STAGE;
        int ku = t * 2 + b_ku;

        uint32_t bH[4][2], bL[4][2];
        #pragma unroll
        for (int p = 0; p < 2; p++) {
            int row = wn * 32 + p * 16 + b_row;
            uint32_t ba = (uint32_t)(row * KU + (ku ^ (row & 7))) * 16;
            LDSM4(bH[2 * p][0], bH[2 * p][1], bH[2 * p + 1][0], bH[2 * p + 1][1], sBh + ba);
            LDSM4(bL[2 * p][0], bL[2 * p][1], bL[2 * p + 1][0], bL[2 * p + 1][1], sBl + ba);
        }
        #pragma unroll
        for (int mt = 0; mt < 4; mt++) {
            uint32_t aH[4], aL[4];
            uint32_t aa = (wm * 64 + mt * 16 + a_row) * A_PITCH + a_kb;
            LDSM4(aH[0], aH[1], aH[2], aH[3], sa + aa);
            LDSM4(aL[0], aL[1], aL[2], aL[3], sa + A_TILE + aa);
            #pragma unroll
            for (int nt = 0; nt < 4; nt++) {
                MMA16816(acc[mt][nt], aH, bH[nt]);
                MMA16816(acc[mt][nt], aH, bL[nt]);
                MMA16816(acc[mt][nt], aL, bH[nt]);
            }
        }
        __syncthreads();
    }

    #pragma unroll
    for (int nt = 0; nt < 4; nt++) {
        int col = nBase + wn * 32 + nt * 8 + tg * 2;
        float b0 = bias[col], b1 = bias[col + 1];
        #pragma unroll
        for (int mt = 0; mt < 4; mt++) {
            int r0 = mBase + wm * 64 + mt * 16 + gr;
            int r1 = r0 + 8;
            float v0 = acc[mt][nt][0] + b0;
            float v1 = acc[mt][nt][1] + b1;
            float v2 = acc[mt][nt][2] + b0;
            float v3 = acc[mt][nt][3] + b1;
            v0 = (v0 >= 0.f) ? v0 : SLOPE * v0;
            v1 = (v1 >= 0.f) ? v1 : SLOPE * v1;
            v2 = (v2 >= 0.f) ? v2 : SLOPE * v2;
            v3 = (v3 >= 0.f) ? v3 : SLOPE * v3;
            if (outF) {
                if (r0 < M) *(float2*)(outF + (size_t)r0 * H + col) = make_float2(v0, v1);
                if (r1 < M) *(float2*)(outF + (size_t)r1 * H + col) = make_float2(v2, v3);
            } else {
                __nv_bfloat162 h0 = __floats2bfloat162_rn(v0, v1);
                __nv_bfloat162 h1 = __floats2bfloat162_rn(v2, v3);
                __nv_bfloat162 l0 = __floats2bfloat162_rn(v0 - __low2float(h0), v1 - __high2float(h0));
                __nv_bfloat162 l1 = __floats2bfloat162_rn(v2 - __low2float(h1), v3 - __high2float(h1));
                if (r0 < M) {
                    *(__nv_bfloat162*)(outH + (size_t)r0 * H + col) = h0;
                    *(__nv_bfloat162*)(outL + (size_t)r0 * H + col) = l0;
                }
                if (r1 < M) {
                    *(__nv_bfloat162*)(outH + (size_t)r1 * H + col) = h1;
                    *(__nv_bfloat162*)(outL + (size_t)r1 * H + col) = l1;
                }
            }
        }
    }
}

// ---------------- launch ----------------
extern "C" void kernel_launch(void* const* d_in, const int* in_sizes, int n_in,
                              void* d_out, int out_size)
{
    const float* x          = (const float*)d_in[0];
    const int*   edge_index = (const int*)  d_in[1];
    const float* w          = (const float*)d_in[2];
    const float* node_w     = (const float*)d_in[3];
    const float* edge_bias  = (const float*)d_in[4];
    const float* le_aw      = (const float*)d_in[5];
    const float* le_ab      = (const float*)d_in[6];
    const float* le_weight  = (const float*)d_in[7];
    const float* le_bias    = (const float*)d_in[8];
    const float* cat1_w     = (const float*)d_in[10];
    const float* cat1_b     = (const float*)d_in[11];
    const float* cat2_w     = (const float*)d_in[12];
    const float* cat2_b     = (const float*)d_in[13];
    const float* nm_w       = (const float*)d_in[14];
    const float* nm_b       = (const float*)d_in[15];
    const float* f1_aw      = (const float*)d_in[16];
    const float* f1_ab      = (const float*)d_in[17];
    const float* f1_weight  = (const float*)d_in[18];
    const float* f1_bias    = (const float*)d_in[19];
    const float* f2_aw      = (const float*)d_in[21];
    const float* f2_ab      = (const float*)d_in[22];
    const float* f2_weight  = (const float*)d_in[23];
    const float* f2_bias    = (const float*)d_in[24];

    int N = in_sizes[3] / H;
    int E = in_sizes[1] / 2;

    float *b2v;
    __nv_bfloat16 *ah, *al, *bh, *bl, *xh, *xl, *wh, *wl, *c1h, *c1l, *nmh, *nml;
    cudaGetSymbolAddress((void**)&b2v, g_b2);
    cudaGetSymbolAddress((void**)&ah,  g_ah);
    cudaGetSymbolAddress((void**)&al,  g_al);
    cudaGetSymbolAddress((void**)&bh,  g_bh);
    cudaGetSymbolAddress((void**)&bl,  g_bl);
    cudaGetSymbolAddress((void**)&xh,  g_xh);
    cudaGetSymbolAddress((void**)&xl,  g_xl);
    cudaGetSymbolAddress((void**)&wh,  g_Wh);
    cudaGetSymbolAddress((void**)&wl,  g_Wl);
    cudaGetSymbolAddress((void**)&c1h, g_C1h);
    cudaGetSymbolAddress((void**)&c1l, g_C1l);
    cudaGetSymbolAddress((void**)&nmh, g_NMh);
    cudaGetSymbolAddress((void**)&nml, g_NMl);

    static bool inited = false;
    static cudaStream_t sA, sB;
    static cudaEvent_t e0, eA, eB;
    if (!inited) {
        cudaFuncSetAttribute(k_gemm_bf, cudaFuncAttributeMaxDynamicSharedMemorySize, 221184);
        cudaStreamCreateWithFlags(&sA, cudaStreamNonBlocking);
        cudaStreamCreateWithFlags(&sB, cudaStreamNonBlocking);
        cudaEventCreateWithFlags(&e0, cudaEventDisableTiming);
        cudaEventCreateWithFlags(&eA, cudaEventDisableTiming);
        cudaEventCreateWithFlags(&eB, cudaEventDisableTiming);
        inited = true;
    }

    // fork side streams off the main (capture) stream
    cudaEventRecord(e0, 0);
    cudaStreamWaitEvent(sA, e0, 0);
    cudaStreamWaitEvent(sB, e0, 0);

    // side stream A: weight preps
    k_styles   <<<dim3(2 * H * RANKV / 8, 3), 256, 0, sA>>>(le_aw, le_ab, f1_aw, f1_ab, f2_aw, f2_ab, w);
    k_modweight<<<dim3(H, 3), 256, 0, sA>>>(le_weight, f1_weight, f2_weight);
    k_prep_c1  <<<H * H / 256, 256, 0, sA>>>(cat1_w);
    k_prep_nm  <<<H, INDIM, 0, sA>>>(nm_w, cat2_w);
    k_prep_b2  <<<1, H, 0, sA>>>(cat1_b, cat2_b, nm_b, cat2_w);
    cudaEventRecord(eA, sA);

    // side stream B: x split
    k_split    <<<(N * INDIM / 4 + 255) / 256, 256, 0, sB>>>(x, xh, xl, N * INDIM / 4);
    cudaEventRecord(eB, sB);

    // main stream: CSR build + gather (fused bias + bf16 split)
    k_zero_deg <<<(N + 255) / 256, 256>>>(N);
    k_hist     <<<(E + 255) / 256, 256>>>(edge_index, E);
    k_scan     <<<1, 1024>>>(N);
    k_fill     <<<(E + 255) / 256, 256>>>(edge_index, E);
    k_gather   <<<(N + 3) / 4, 256>>>(node_w, edge_bias, ah, al, N);

    // join
    cudaStreamWaitEvent(0, eA, 0);
    cudaStreamWaitEvent(0, eB, 0);

    dim3 gg((N + 127) / 128, 2);
    const int SM256 = 2 * (128 * 32 * 16) + 2 * A_STAGE;   // 155648
    const int SM384 = 2 * (128 * 48 * 16) + 2 * A_STAGE;   // 221184
    // G1: b = leaky(agg @ W_le^T + le_bias)
    k_gemm_bf<<<gg, 256, SM256>>>(ah, al, H, nullptr, nullptr, 0,
                                  wh + 0 * H * H, wl + 0 * H * H, nullptr, nullptr,
                                  nullptr, bh, bl, N, le_bias);
    // G2: a = leaky(b @ (I+cat1^T) + x @ NM + b2)
    k_gemm_bf<<<gg, 256, SM384>>>(bh, bl, H, xh, xl, INDIM,
                                  c1h, c1l, nmh, nml,
                                  nullptr, ah, al, N, b2v);
    // G3: b = leaky(a @ W_f1^T + f1_bias)
    k_gemm_bf<<<gg, 256, SM256>>>(ah, al, H, nullptr, nullptr, 0,
                                  wh + 1 * H * H, wl + 1 * H * H, nullptr, nullptr,
                                  nullptr, bh, bl, N, f1_bias);
    // G4: out = leaky(b @ W_f2^T + f2_bias)
    k_gemm_bf<<<gg, 256, SM256>>>(bh, bl, H, nullptr, nullptr, 0,
                                  wh + 2 * H * H, wl + 2 * H * H, nullptr, nullptr,
                                  (float*)d_out, nullptr, nullptr, N, f2_bias);
}